// round 7
// baseline (speedup 1.0000x reference)
#include <cuda_runtime.h>
#include <cstdint>
#include <cstddef>

// Problem constants
#define T_STEPS 2048
#define BATCH   16
#define DIM     1024
#define NDIM    64
#define PROJ    256            // 4 * NDIM (k, v, q, a)
#define PSTRIDE 4096           // floats per time step = BATCH * PROJ
#define LOG2E   1.44269504f

// Scratch: projections P[(t*BATCH + b)*256 + c], c = {k:0..63, v:64..127, q:128..191, a:192..255}
__device__ float g_P[(size_t)T_STEPS * BATCH * PROJ];   // 33.5 MB

// ---------------------------------------------------------------------------
// Kernel 1: fused projection GEMM (scalar FFMA — at the fp32 roofline).
// ---------------------------------------------------------------------------
__global__ __launch_bounds__(128) void proj_gemm(
    const float* __restrict__ x,
    const float* __restrict__ Wk, const float* __restrict__ Wv,
    const float* __restrict__ Wq, const float* __restrict__ Wa)
{
    __shared__ float As[16][128];   // [k][m]
    __shared__ float Bs[16][64];    // [k][c]

    const int tid = threadIdx.x;
    const int m0  = blockIdx.x * 128;
    const int c0  = blockIdx.y * 64;
    const float* W = (blockIdx.y == 0) ? Wk :
                     (blockIdx.y == 1) ? Wv :
                     (blockIdx.y == 2) ? Wq : Wa;

    const int tx = tid & 7;    // c sub-tile (0..7)
    const int ty = tid >> 3;   // m sub-tile (0..15)

    float acc[8][8];
#pragma unroll
    for (int a = 0; a < 8; a++)
#pragma unroll
        for (int b = 0; b < 8; b++) acc[a][b] = 0.0f;

    const float* xrow = x + (size_t)(m0 + tid) * DIM;
    const int    brow = tid >> 1;
    const int    bcol = (tid & 1) * 8;
    const float* wrow = W + (size_t)brow * DIM + bcol;

    for (int k0 = 0; k0 < DIM; k0 += 16) {
        float4 a0 = *(const float4*)(xrow + k0);
        float4 a1 = *(const float4*)(xrow + k0 + 4);
        float4 a2 = *(const float4*)(xrow + k0 + 8);
        float4 a3 = *(const float4*)(xrow + k0 + 12);
        float4 b0 = *(const float4*)(wrow + k0);
        float4 b1 = *(const float4*)(wrow + k0 + 4);

        __syncthreads();
        As[ 0][tid] = a0.x; As[ 1][tid] = a0.y; As[ 2][tid] = a0.z; As[ 3][tid] = a0.w;
        As[ 4][tid] = a1.x; As[ 5][tid] = a1.y; As[ 6][tid] = a1.z; As[ 7][tid] = a1.w;
        As[ 8][tid] = a2.x; As[ 9][tid] = a2.y; As[10][tid] = a2.z; As[11][tid] = a2.w;
        As[12][tid] = a3.x; As[13][tid] = a3.y; As[14][tid] = a3.z; As[15][tid] = a3.w;
        Bs[bcol + 0][brow] = b0.x; Bs[bcol + 1][brow] = b0.y;
        Bs[bcol + 2][brow] = b0.z; Bs[bcol + 3][brow] = b0.w;
        Bs[bcol + 4][brow] = b1.x; Bs[bcol + 5][brow] = b1.y;
        Bs[bcol + 6][brow] = b1.z; Bs[bcol + 7][brow] = b1.w;
        __syncthreads();

#pragma unroll
        for (int k = 0; k < 16; k++) {
            float af[8], bf[8];
            *(float4*)(af)     = *(const float4*)&As[k][ty * 8];
            *(float4*)(af + 4) = *(const float4*)&As[k][ty * 8 + 4];
            *(float4*)(bf)     = *(const float4*)&Bs[k][tx * 8];
            *(float4*)(bf + 4) = *(const float4*)&Bs[k][tx * 8 + 4];
#pragma unroll
            for (int im = 0; im < 8; im++)
#pragma unroll
                for (int ic = 0; ic < 8; ic++)
                    acc[im][ic] = fmaf(af[im], bf[ic], acc[im][ic]);
        }
    }

#pragma unroll
    for (int im = 0; im < 8; im++) {
        float* dst = g_P + (size_t)(m0 + ty * 8 + im) * PROJ + c0 + tx * 8;
        *(float4*)(dst)     = make_float4(acc[im][0], acc[im][1], acc[im][2], acc[im][3]);
        *(float4*)(dst + 4) = make_float4(acc[im][4], acc[im][5], acc[im][6], acc[im][7]);
    }
}

// ---------------------------------------------------------------------------
// Kernel 2: scan, 32 lanes/row (2 cols each), 8 rows per 256-thr CTA,
// 128 CTAs -> 1024 warps (~2 per SMSP: cross-warp stall hiding).
// TWO-step algebraic lookahead — SHFL-free carried chain (same as R6):
//   retrieved(t) = a(t-1)*M(t) + (1-a(t-1))*G1(t)
//   M(t)         = a(t-2)*A(t) + (1-a(t-2))*G2(t)
//   A(t)  = S(t-3).k(t)            [3-step slack for its shuffle tree]
//   G1(t) = v(t-1)*(k(t-1).k(t))   [k.k dots at refill time, 4-step slack]
//   G2(t) = v(t-2)*(k(t-2).k(t))
//   out(t) = S(t).q(t) post-update (off-chain)
// ---------------------------------------------------------------------------
__device__ __forceinline__ float tree32(float s)
{
    s += __shfl_xor_sync(0xffffffffu, s, 1);
    s += __shfl_xor_sync(0xffffffffu, s, 2);
    s += __shfl_xor_sync(0xffffffffu, s, 4);
    s += __shfl_xor_sync(0xffffffffu, s, 8);
    s += __shfl_xor_sync(0xffffffffu, s, 16);
    return s;
}

__device__ __forceinline__ float dot2(const float (&a)[2], const float (&b)[2])
{
    return fmaf(a[1], b[1], a[0] * b[0]);
}

__device__ __forceinline__ float sigmoid_neg_l2(float z2)  // z2 = -log2(e)*z
{
    float e;
    asm("ex2.approx.f32 %0, %1;" : "=f"(e) : "f"(z2));
    float den = 1.0f + e;
    float r;
    asm("rcp.approx.f32 %0, %1;" : "=f"(r) : "f"(den));
    return r;
}

__device__ __forceinline__ void load_slot(const float* __restrict__ Pb, int t,
                                          int i, int lane, float cb,
                                          float (&k)[2], float (&q)[2],
                                          float& v, float& c0)
{
    const float* p = Pb + (size_t)t * PSTRIDE;
    float2 kv = *(const float2*)(p + lane * 2);
    float2 qv = *(const float2*)(p + 128 + lane * 2);
    k[0] = kv.x; k[1] = kv.y;
    q[0] = qv.x; q[1] = qv.y;
    v  = p[64 + i];
    c0 = fmaf(-LOG2E, p[192 + i], cb);   // -log2(e)*(a + b_alpha)
}

__global__ __launch_bounds__(256, 1) void scan_kernel(
    const float* __restrict__ S0,
    const float* __restrict__ dA, const float* __restrict__ bA,
    float* __restrict__ out, float* __restrict__ Sout, int writeS)
{
    const int tid  = threadIdx.x;
    const int b    = blockIdx.x >> 3;                 // batch 0..15
    const int rb   = blockIdx.x & 7;                  // row block (8 rows)
    const int row  = tid >> 5;                        // warp = local row 0..7
    const int lane = tid & 31;                        // col slice (2 cols)
    const int i    = rb * 8 + row;                    // global row 0..63

    const float* Pb = g_P + b * PROJ;
    const float cb  = -LOG2E * bA[i];
    const float c1  = -LOG2E * dA[i];

    float S[2];
    {
        float2 s = *(const float2*)(S0 + ((size_t)b * NDIM + i) * NDIM + lane * 2);
        S[0] = s.x; S[1] = s.y;
    }

    // ring-of-4 buffers
    float kb[4][2], qb[4][2], vb[4], c0b[4];
    float kk1b[4], kk2b[4], Ar[4];
#pragma unroll
    for (int s = 0; s < 4; s++)
        load_slot(Pb, s, i, lane, cb, kb[s], qb[s], vb[s], c0b[s]);

    kk1b[0] = 0.0f;
    kk1b[1] = tree32(dot2(kb[0], kb[1]));
    kk1b[2] = tree32(dot2(kb[1], kb[2]));
    kk1b[3] = tree32(dot2(kb[2], kb[3]));
    kk2b[0] = 0.0f;
    kk2b[1] = 0.0f;
    kk2b[2] = tree32(dot2(kb[0], kb[2]));
    kk2b[3] = tree32(dot2(kb[1], kb[3]));

    Ar[0] = 0.0f;                        // A(4): written at step 1
    Ar[1] = tree32(dot2(S, kb[1]));      // A(1) = S0.k(1)
    Ar[2] = tree32(dot2(S, kb[2]));      // A(2) = S0.k(2)
    Ar[3] = 0.0f;                        // A(3): written at step 0

    // virtual history: alpha(-1)=alpha(-2)=1, v(-1)=v(-2)=0
    float alpha_prev = 1.0f;
    float vprev      = 0.0f;
    float dM         = tree32(dot2(S, kb[0]));   // M(0)-G1(0) = S0.k(0)
    float G1cur      = 0.0f;
    float c0cur      = c0b[0];

    float* orow = out + (size_t)b * NDIM + i;

#pragma unroll 1
    for (int t = 0; t < T_STEPS; t += 4) {
#pragma unroll
        for (int c = 0; c < 4; c++) {
            const int tt  = t + c;
            const int cn  = (c + 1) & 3;
            const int cp2 = (c + 2) & 3;
            const int cp3 = (c + 3) & 3;
            const float vcur = vb[c];

            // ---- off-chain: vk, D = S - vk ----
            float vk[2], D[2];
#pragma unroll
            for (int j = 0; j < 2; j++) vk[j] = vcur * kb[c][j];
#pragma unroll
            for (int j = 0; j < 2; j++) D[j] = S[j] - vk[j];

            // ---- carried chain: alpha(t) ----
            float retrieved = fmaf(alpha_prev, dM, G1cur);
            float z2        = fmaf(c1, retrieved, c0cur);
            float alpha     = sigmoid_neg_l2(z2);

            // ---- M(t+1) branch (uses alpha_prev, NOT alpha) ----
            float G2n   = vprev * kk2b[cn];
            float Mnext = fmaf(alpha_prev, Ar[cn] - G2n, G2n);

            // ---- S(t) = alpha*D + vk ----
#pragma unroll
            for (int j = 0; j < 2; j++) S[j] = fmaf(alpha, D[j], vk[j]);

            // ---- A(t+3) = S(t).k(t+3)  (3-step slack) ----
            Ar[cp3] = tree32(dot2(S, kb[cp3]));

            // ---- out(t) = S(t).q(t), off-chain ----
            float o   = tree32(dot2(S, qb[c]));
            float res = o * o * sigmoid_neg_l2(-LOG2E * o);
            if (lane == 0)
                orow[(size_t)tt * (BATCH * NDIM)] = res;

            // ---- refill slot c with step tt+4; kk dots (4-step slack) ----
            {
                int t4 = tt + 4; if (t4 > T_STEPS - 1) t4 = T_STEPS - 1;
                float kn[2], qn[2], vn, c0n;
                load_slot(Pb, t4, i, lane, cb, kn, qn, vn, c0n);
                kk1b[c] = tree32(dot2(kb[cp3], kn));   // k(t+3).k(t+4)
                kk2b[c] = tree32(dot2(kb[cp2], kn));   // k(t+2).k(t+4)
                kb[c][0] = kn[0]; kb[c][1] = kn[1];
                qb[c][0] = qn[0]; qb[c][1] = qn[1];
                vb[c] = vn; c0b[c] = c0n;
                int tp = tt + 16; if (tp > T_STEPS - 1) tp = T_STEPS - 1;
                const float* pf = Pb + (size_t)tp * PSTRIDE + lane * 8;
                asm volatile("prefetch.global.L2 [%0];" :: "l"(pf));
            }

            // ---- carries for step t+1 ----
            float G1n = vcur * kk1b[cn];     // v(t)*k(t).k(t+1)
            dM        = Mnext - G1n;
            G1cur     = G1n;
            vprev     = vcur;
            alpha_prev = alpha;
            c0cur     = c0b[cn];
        }
    }

    if (writeS) {
        float* sp = Sout + ((size_t)b * NDIM + i) * NDIM + lane * 2;
        *(float2*)sp = make_float2(S[0], S[1]);
    }
}

// ---------------------------------------------------------------------------
extern "C" void kernel_launch(void* const* d_in, const int* in_sizes, int n_in,
                              void* d_out, int out_size)
{
    const float* x  = (const float*)d_in[0];
    const float* S0 = (const float*)d_in[1];
    const float* Wk = (const float*)d_in[2];
    const float* Wv = (const float*)d_in[3];
    const float* Wq = (const float*)d_in[4];
    const float* Wa = (const float*)d_in[5];
    const float* dA = (const float*)d_in[6];
    const float* bA = (const float*)d_in[7];

    float* out = (float*)d_out;
    const size_t out_elems = (size_t)T_STEPS * BATCH * NDIM;          // 2,097,152
    const size_t s_elems   = (size_t)BATCH * NDIM * NDIM;             //    65,536
    int writeS = ((size_t)out_size >= out_elems + s_elems) ? 1 : 0;
    float* Sout = out + out_elems;

    dim3 grid_g(T_STEPS * BATCH / 128, 4);   // (256, 4)
    proj_gemm<<<grid_g, 128>>>(x, Wk, Wv, Wq, Wa);

    scan_kernel<<<128, 256>>>(S0, dA, bA, out, Sout, writeS);
}

// round 9
// speedup vs baseline: 1.0168x; 1.0168x over previous
#include <cuda_runtime.h>
#include <cstdint>
#include <cstddef>

// Problem constants
#define T_STEPS 2048
#define BATCH   16
#define DIM     1024
#define NDIM    64
#define PROJ    256            // 4 * NDIM (k, v, q, a)
#define PSTRIDE 4096           // floats per time step = BATCH * PROJ
#define LOG2E   1.44269504f

#define NCHUNK     256         // 2048 steps / 8 steps per chunk
#define KSPLIT     4
#define SCAN_BLKS  128
#define GEMM_BLKS  (256 * 4 * KSPLIT)   // 4096: (mchunk, proj, ksplit)
#define FLAG_TARGET (4 * KSPLIT)        // 16 sub-blocks per chunk

// Scratch: projections P[(t*BATCH + b)*256 + c], c = {k:0..63, v:64..127, q:128..191, a:192..255}
__device__ float g_P[(size_t)T_STEPS * BATCH * PROJ];   // 33.5 MB
__device__ int   g_flag[NCHUNK];

// ---------------------------------------------------------------------------
// Init: zero P (atomic accumulation target) and chunk flags.
// ---------------------------------------------------------------------------
__global__ void init_kernel()
{
    const size_t n4 = (size_t)T_STEPS * BATCH * PROJ / 4;
    float4* p = (float4*)g_P;
    for (size_t idx = (size_t)blockIdx.x * blockDim.x + threadIdx.x;
         idx < n4; idx += (size_t)gridDim.x * blockDim.x)
        p[idx] = make_float4(0.f, 0.f, 0.f, 0.f);
    if (blockIdx.x == 0 && threadIdx.x < NCHUNK)
        g_flag[threadIdx.x] = 0;
}

// ---------------------------------------------------------------------------
// GEMM part: one (mchunk, proj, ksplit) tile.  BM=128, BN=64, K-range=256.
// Accumulate into g_P with atomicAdd; publish chunk flag on completion.
// ---------------------------------------------------------------------------
__device__ __forceinline__ void gemm_part(
    int gbid,
    const float* __restrict__ x,
    const float* __restrict__ Wk, const float* __restrict__ Wv,
    const float* __restrict__ Wq, const float* __restrict__ Wa,
    float (&As)[16][128], float (&Bs)[16][64])
{
    const int chunk = gbid >> 4;          // 0..255, fast-completing in order
    const int sub   = gbid & 15;
    const int proj  = sub & 3;
    const int ks    = sub >> 2;

    const int tid = threadIdx.x;
    const int m0  = chunk * 128;
    const int c0  = proj * 64;
    const float* W = (proj == 0) ? Wk : (proj == 1) ? Wv : (proj == 2) ? Wq : Wa;

    const int tx = tid & 7;
    const int ty = tid >> 3;

    float acc[8][8];
#pragma unroll
    for (int a = 0; a < 8; a++)
#pragma unroll
        for (int b = 0; b < 8; b++) acc[a][b] = 0.0f;

    const float* xrow = x + (size_t)(m0 + tid) * DIM;
    const int    brow = tid >> 1;
    const int    bcol = (tid & 1) * 8;
    const float* wrow = W + (size_t)brow * DIM + bcol;

    const int kbeg = ks * (DIM / KSPLIT);
    const int kend = kbeg + (DIM / KSPLIT);

    for (int k0 = kbeg; k0 < kend; k0 += 16) {
        float4 a0 = *(const float4*)(xrow + k0);
        float4 a1 = *(const float4*)(xrow + k0 + 4);
        float4 a2 = *(const float4*)(xrow + k0 + 8);
        float4 a3 = *(const float4*)(xrow + k0 + 12);
        float4 b0 = *(const float4*)(wrow + k0);
        float4 b1 = *(const float4*)(wrow + k0 + 4);

        __syncthreads();
        As[ 0][tid] = a0.x; As[ 1][tid] = a0.y; As[ 2][tid] = a0.z; As[ 3][tid] = a0.w;
        As[ 4][tid] = a1.x; As[ 5][tid] = a1.y; As[ 6][tid] = a1.z; As[ 7][tid] = a1.w;
        As[ 8][tid] = a2.x; As[ 9][tid] = a2.y; As[10][tid] = a2.z; As[11][tid] = a2.w;
        As[12][tid] = a3.x; As[13][tid] = a3.y; As[14][tid] = a3.z; As[15][tid] = a3.w;
        Bs[bcol + 0][brow] = b0.x; Bs[bcol + 1][brow] = b0.y;
        Bs[bcol + 2][brow] = b0.z; Bs[bcol + 3][brow] = b0.w;
        Bs[bcol + 4][brow] = b1.x; Bs[bcol + 5][brow] = b1.y;
        Bs[bcol + 6][brow] = b1.z; Bs[bcol + 7][brow] = b1.w;
        __syncthreads();

#pragma unroll
        for (int k = 0; k < 16; k++) {
            float af[8], bf[8];
            *(float4*)(af)     = *(const float4*)&As[k][ty * 8];
            *(float4*)(af + 4) = *(const float4*)&As[k][ty * 8 + 4];
            *(float4*)(bf)     = *(const float4*)&Bs[k][tx * 8];
            *(float4*)(bf + 4) = *(const float4*)&Bs[k][tx * 8 + 4];
#pragma unroll
            for (int im = 0; im < 8; im++)
#pragma unroll
                for (int ic = 0; ic < 8; ic++)
                    acc[im][ic] = fmaf(af[im], bf[ic], acc[im][ic]);
        }
    }

    // accumulate (K-split partial) into P
#pragma unroll
    for (int im = 0; im < 8; im++) {
        float* dst = g_P + (size_t)(m0 + ty * 8 + im) * PROJ + c0 + tx * 8;
#pragma unroll
        for (int ic = 0; ic < 8; ic++)
            atomicAdd(dst + ic, acc[im][ic]);
    }

    __threadfence();
    __syncthreads();
    if (tid == 0)
        atomicAdd(&g_flag[chunk], 1);
}

// ---------------------------------------------------------------------------
// Scan part (R6 geometry: 16 lanes/row, 8 rows per 128-thr CTA, 128 CTAs).
// Two-step algebraic lookahead — SHFL-free carried chain.
// Waits on chunk flags; P is L2-resident (REDG-produced).
// ---------------------------------------------------------------------------
__device__ __forceinline__ float tree16(float s)
{
    s += __shfl_xor_sync(0xffffffffu, s, 1);
    s += __shfl_xor_sync(0xffffffffu, s, 2);
    s += __shfl_xor_sync(0xffffffffu, s, 4);
    s += __shfl_xor_sync(0xffffffffu, s, 8);
    return s;
}

__device__ __forceinline__ float dot4(const float (&a)[4], const float (&b)[4])
{
    float s0 = a[0] * b[0];
    float s1 = a[1] * b[1];
    s0 = fmaf(a[2], b[2], s0);
    s1 = fmaf(a[3], b[3], s1);
    return s0 + s1;
}

__device__ __forceinline__ float sigmoid_neg_l2(float z2)  // z2 = -log2(e)*z
{
    float e;
    asm("ex2.approx.f32 %0, %1;" : "=f"(e) : "f"(z2));
    float den = 1.0f + e;
    float r;
    asm("rcp.approx.f32 %0, %1;" : "=f"(r) : "f"(den));
    return r;
}

__device__ __forceinline__ void wait_chunk(int chunk)
{
    if (threadIdx.x == 0) {
        int v;
        unsigned ns = 64;
        while (true) {
            asm volatile("ld.acquire.gpu.global.b32 %0, [%1];"
                         : "=r"(v) : "l"(g_flag + chunk) : "memory");
            if (v >= FLAG_TARGET) break;
            __nanosleep(ns);
            if (ns < 4096) ns <<= 1;
        }
    }
    __syncthreads();
}

__device__ __forceinline__ void load_slot(const float* __restrict__ Pb, int t,
                                          int i, int lane16, float cb,
                                          float (&k)[4], float (&q)[4],
                                          float& v, float& c0)
{
    const float* p = Pb + (size_t)t * PSTRIDE;
    float4 kv = *(const float4*)(p + lane16 * 4);
    float4 qv = *(const float4*)(p + 128 + lane16 * 4);
    k[0] = kv.x; k[1] = kv.y; k[2] = kv.z; k[3] = kv.w;
    q[0] = qv.x; q[1] = qv.y; q[2] = qv.z; q[3] = qv.w;
    v  = p[64 + i];
    c0 = fmaf(-LOG2E, p[192 + i], cb);   // -log2(e)*(a + b_alpha)
}

__device__ __forceinline__ void scan_part(
    const float* __restrict__ S0,
    const float* __restrict__ dA, const float* __restrict__ bA,
    float* __restrict__ out, float* __restrict__ Sout, int writeS)
{
    const int tid    = threadIdx.x;
    const int b      = blockIdx.x >> 3;                 // batch 0..15
    const int rb     = blockIdx.x & 7;                  // row block (8 rows)
    const int row    = tid >> 4;                        // local row 0..7
    const int lane16 = tid & 15;                        // col slice (4 cols)
    const int i      = rb * 8 + row;                    // global row 0..63

    const float* Pb = g_P + b * PROJ;
    const float cb  = -LOG2E * bA[i];
    const float c1  = -LOG2E * dA[i];

    float S[4];
    {
        float4 s = *(const float4*)(S0 + ((size_t)b * NDIM + i) * NDIM + lane16 * 4);
        S[0] = s.x; S[1] = s.y; S[2] = s.z; S[3] = s.w;
    }

    wait_chunk(0);   // steps 0..7 available (prologue needs 0..3)

    // ring-of-4 buffers
    float kb[4][4], qb[4][4], vb[4], c0b[4];
    float kk1b[4], kk2b[4], Ar[4];
#pragma unroll
    for (int s = 0; s < 4; s++)
        load_slot(Pb, s, i, lane16, cb, kb[s], qb[s], vb[s], c0b[s]);

    kk1b[0] = 0.0f;
    kk1b[1] = tree16(dot4(kb[0], kb[1]));
    kk1b[2] = tree16(dot4(kb[1], kb[2]));
    kk1b[3] = tree16(dot4(kb[2], kb[3]));
    kk2b[0] = 0.0f;
    kk2b[1] = 0.0f;
    kk2b[2] = tree16(dot4(kb[0], kb[2]));
    kk2b[3] = tree16(dot4(kb[1], kb[3]));

    Ar[0] = 0.0f;                        // A(4): written at step 1
    Ar[1] = tree16(dot4(S, kb[1]));      // A(1) = S0.k(1)
    Ar[2] = tree16(dot4(S, kb[2]));      // A(2) = S0.k(2)
    Ar[3] = 0.0f;                        // A(3): written at step 0

    // virtual history: alpha(-1)=alpha(-2)=1, v(-1)=v(-2)=0
    float alpha_prev = 1.0f;
    float vprev      = 0.0f;
    float dM         = tree16(dot4(S, kb[0]));   // M(0)-G1(0) = S0.k(0)
    float G1cur      = 0.0f;
    float c0cur      = c0b[0];

    float* orow = out + (size_t)b * NDIM + i;

#pragma unroll 1
    for (int t = 0; t < T_STEPS; t += 8) {
        // refills during this group load steps t+4 .. t+11  -> chunk t/8 + 1
        int need = (t >> 3) + 1; if (need > NCHUNK - 1) need = NCHUNK - 1;
        wait_chunk(need);

#pragma unroll
        for (int cc = 0; cc < 8; cc++) {
            const int tt  = t + cc;
            const int c   = cc & 3;
            const int cn  = (cc + 1) & 3;
            const int cp2 = (cc + 2) & 3;
            const int cp3 = (cc + 3) & 3;
            const float vcur = vb[c];

            // ---- off-chain: vk, D = S - vk ----
            float vk[4], D[4];
#pragma unroll
            for (int j = 0; j < 4; j++) vk[j] = vcur * kb[c][j];
#pragma unroll
            for (int j = 0; j < 4; j++) D[j] = S[j] - vk[j];

            // ---- carried chain: alpha(t) ----
            float retrieved = fmaf(alpha_prev, dM, G1cur);
            float z2        = fmaf(c1, retrieved, c0cur);
            float alpha     = sigmoid_neg_l2(z2);

            // ---- M(t+1) branch (uses alpha_prev, NOT alpha) ----
            float G2n   = vprev * kk2b[cn];
            float Mnext = fmaf(alpha_prev, Ar[cn] - G2n, G2n);

            // ---- S(t) = alpha*D + vk ----
#pragma unroll
            for (int j = 0; j < 4; j++) S[j] = fmaf(alpha, D[j], vk[j]);

            // ---- A(t+3) = S(t).k(t+3)  (3-step slack) ----
            Ar[cp3] = tree16(dot4(S, kb[cp3]));

            // ---- out(t) = S(t).q(t), off-chain ----
            float o   = tree16(dot4(S, qb[c]));
            float res = o * o * sigmoid_neg_l2(-LOG2E * o);
            if (lane16 == 0)
                orow[(size_t)tt * (BATCH * NDIM)] = res;

            // ---- refill slot c with step tt+4; kk dots (4-step slack) ----
            {
                int t4 = tt + 4; if (t4 > T_STEPS - 1) t4 = T_STEPS - 1;
                float kn[4];
                load_slot(Pb, t4, i, lane16, cb, kn, qb[c], vb[c], c0b[c]);
                kk1b[c] = tree16(dot4(kb[cp3], kn));   // k(t+3).k(t+4)
                kk2b[c] = tree16(dot4(kb[cp2], kn));   // k(t+2).k(t+4)
#pragma unroll
                for (int j = 0; j < 4; j++) kb[c][j] = kn[j];
            }

            // ---- carries for step t+1 ----
            float G1n = vcur * kk1b[cn];     // v(t)*k(t).k(t+1)
            dM        = Mnext - G1n;
            G1cur     = G1n;
            vprev     = vcur;
            alpha_prev = alpha;
            c0cur     = c0b[cn];
        }
    }

    if (writeS) {
        float* sp = Sout + ((size_t)b * NDIM + i) * NDIM + lane16 * 4;
        *(float4*)sp = make_float4(S[0], S[1], S[2], S[3]);
    }
}

// ---------------------------------------------------------------------------
// Fused kernel: blocks 0..127 = scan (resident in wave 1), 128.. = GEMM.
// ---------------------------------------------------------------------------
__global__ __launch_bounds__(128) void fused_kernel(
    const float* __restrict__ x,  const float* __restrict__ S0,
    const float* __restrict__ Wk, const float* __restrict__ Wv,
    const float* __restrict__ Wq, const float* __restrict__ Wa,
    const float* __restrict__ dA, const float* __restrict__ bA,
    float* __restrict__ out, float* __restrict__ Sout, int writeS)
{
    __shared__ float As[16][128];
    __shared__ float Bs[16][64];

    if (blockIdx.x < SCAN_BLKS) {
        scan_part(S0, dA, bA, out, Sout, writeS);
    } else {
        gemm_part((int)blockIdx.x - SCAN_BLKS, x, Wk, Wv, Wq, Wa, As, Bs);
    }
}

// ---------------------------------------------------------------------------
extern "C" void kernel_launch(void* const* d_in, const int* in_sizes, int n_in,
                              void* d_out, int out_size)
{
    const float* x  = (const float*)d_in[0];
    const float* S0 = (const float*)d_in[1];
    const float* Wk = (const float*)d_in[2];
    const float* Wv = (const float*)d_in[3];
    const float* Wq = (const float*)d_in[4];
    const float* Wa = (const float*)d_in[5];
    const float* dA = (const float*)d_in[6];
    const float* bA = (const float*)d_in[7];

    float* out = (float*)d_out;
    const size_t out_elems = (size_t)T_STEPS * BATCH * NDIM;          // 2,097,152
    const size_t s_elems   = (size_t)BATCH * NDIM * NDIM;             //    65,536
    int writeS = ((size_t)out_size >= out_elems + s_elems) ? 1 : 0;
    float* Sout = out + out_elems;

    init_kernel<<<1024, 256>>>();
    fused_kernel<<<SCAN_BLKS + GEMM_BLKS, 128>>>(x, S0, Wk, Wv, Wq, Wa,
                                                 dA, bA, out, Sout, writeS);
}

// round 10
// speedup vs baseline: 1.1364x; 1.1176x over previous
#include <cuda_runtime.h>
#include <cstdint>
#include <cstddef>

// Problem constants
#define T_STEPS 2048
#define BATCH   16
#define DIM     1024
#define NDIM    64
#define PROJ    256            // 4 * NDIM (k, v, q, a)
#define PSTRIDE 4096           // floats per time step = BATCH * PROJ
#define LOG2E   1.44269504f

// Scratch: projections P[(t*BATCH + b)*256 + c], c = {k:0..63, v:64..127, q:128..191, a:192..255}
__device__ float  g_P[(size_t)T_STEPS * BATCH * PROJ];   // 33.5 MB
__device__ float2 g_kk[(size_t)BATCH * T_STEPS];         // (k(t-1).k(t), k(t-2).k(t))

// ---------------------------------------------------------------------------
// Kernel 1: fused projection GEMM (scalar FFMA — at the fp32 roofline).
// ---------------------------------------------------------------------------
__global__ __launch_bounds__(128) void proj_gemm(
    const float* __restrict__ x,
    const float* __restrict__ Wk, const float* __restrict__ Wv,
    const float* __restrict__ Wq, const float* __restrict__ Wa)
{
    __shared__ float As[16][128];   // [k][m]
    __shared__ float Bs[16][64];    // [k][c]

    const int tid = threadIdx.x;
    const int m0  = blockIdx.x * 128;
    const int c0  = blockIdx.y * 64;
    const float* W = (blockIdx.y == 0) ? Wk :
                     (blockIdx.y == 1) ? Wv :
                     (blockIdx.y == 2) ? Wq : Wa;

    const int tx = tid & 7;    // c sub-tile (0..7)
    const int ty = tid >> 3;   // m sub-tile (0..15)

    float acc[8][8];
#pragma unroll
    for (int a = 0; a < 8; a++)
#pragma unroll
        for (int b = 0; b < 8; b++) acc[a][b] = 0.0f;

    const float* xrow = x + (size_t)(m0 + tid) * DIM;
    const int    brow = tid >> 1;
    const int    bcol = (tid & 1) * 8;
    const float* wrow = W + (size_t)brow * DIM + bcol;

    for (int k0 = 0; k0 < DIM; k0 += 16) {
        float4 a0 = *(const float4*)(xrow + k0);
        float4 a1 = *(const float4*)(xrow + k0 + 4);
        float4 a2 = *(const float4*)(xrow + k0 + 8);
        float4 a3 = *(const float4*)(xrow + k0 + 12);
        float4 b0 = *(const float4*)(wrow + k0);
        float4 b1 = *(const float4*)(wrow + k0 + 4);

        __syncthreads();
        As[ 0][tid] = a0.x; As[ 1][tid] = a0.y; As[ 2][tid] = a0.z; As[ 3][tid] = a0.w;
        As[ 4][tid] = a1.x; As[ 5][tid] = a1.y; As[ 6][tid] = a1.z; As[ 7][tid] = a1.w;
        As[ 8][tid] = a2.x; As[ 9][tid] = a2.y; As[10][tid] = a2.z; As[11][tid] = a2.w;
        As[12][tid] = a3.x; As[13][tid] = a3.y; As[14][tid] = a3.z; As[15][tid] = a3.w;
        Bs[bcol + 0][brow] = b0.x; Bs[bcol + 1][brow] = b0.y;
        Bs[bcol + 2][brow] = b0.z; Bs[bcol + 3][brow] = b0.w;
        Bs[bcol + 4][brow] = b1.x; Bs[bcol + 5][brow] = b1.y;
        Bs[bcol + 6][brow] = b1.z; Bs[bcol + 7][brow] = b1.w;
        __syncthreads();

#pragma unroll
        for (int k = 0; k < 16; k++) {
            float af[8], bf[8];
            *(float4*)(af)     = *(const float4*)&As[k][ty * 8];
            *(float4*)(af + 4) = *(const float4*)&As[k][ty * 8 + 4];
            *(float4*)(bf)     = *(const float4*)&Bs[k][tx * 8];
            *(float4*)(bf + 4) = *(const float4*)&Bs[k][tx * 8 + 4];
#pragma unroll
            for (int im = 0; im < 8; im++)
#pragma unroll
                for (int ic = 0; ic < 8; ic++)
                    acc[im][ic] = fmaf(af[im], bf[ic], acc[im][ic]);
        }
    }

#pragma unroll
    for (int im = 0; im < 8; im++) {
        float* dst = g_P + (size_t)(m0 + ty * 8 + im) * PROJ + c0 + tx * 8;
        *(float4*)(dst)     = make_float4(acc[im][0], acc[im][1], acc[im][2], acc[im][3]);
        *(float4*)(dst + 4) = make_float4(acc[im][4], acc[im][5], acc[im][6], acc[im][7]);
    }
}

// ---------------------------------------------------------------------------
// Kernel 1b: row-independent k.k lookahead dots.
//   g_kk[b][t] = ( k(t-1).k(t),  k(t-2).k(t) )   (0 where t-1/t-2 < 0)
// One warp per (b,t): 2 elems/lane, 2 dots, 2 tree32, one float2 store.
// ---------------------------------------------------------------------------
__global__ __launch_bounds__(256) void kk_kernel()
{
    const int w    = (blockIdx.x * 256 + threadIdx.x) >> 5;   // global warp
    const int lane = threadIdx.x & 31;
    const int b    = w >> 11;          // 2048 warps per batch
    const int t    = w & 2047;

    const float* kt = g_P + b * PROJ + (size_t)t * PSTRIDE;
    float2 k0 = *(const float2*)(kt + lane * 2);
    float2 k1 = make_float2(0.f, 0.f);
    float2 k2 = make_float2(0.f, 0.f);
    if (t >= 1) k1 = *(const float2*)(kt - PSTRIDE + lane * 2);
    if (t >= 2) k2 = *(const float2*)(kt - 2 * PSTRIDE + lane * 2);

    float d1 = fmaf(k0.y, k1.y, k0.x * k1.x);
    float d2 = fmaf(k0.y, k2.y, k0.x * k2.x);
#pragma unroll
    for (int m = 1; m < 32; m <<= 1) {
        d1 += __shfl_xor_sync(0xffffffffu, d1, m);
        d2 += __shfl_xor_sync(0xffffffffu, d2, m);
    }
    if (lane == 0)
        g_kk[b * T_STEPS + t] = make_float2(d1, d2);
}

// ---------------------------------------------------------------------------
// Kernel 2: scan, 16 lanes/row (4 cols each), 8 rows per 128-thr CTA, 128 CTAs.
// Two-step algebraic lookahead, k.k dots PRECOMPUTED (2 trees/step, 8 SHFL):
//   retrieved(t) = a(t-1)*M(t) + (1-a(t-1))*G1(t)
//   M(t)         = a(t-2)*A(t) + (1-a(t-2))*G2(t)
//   A(t)  = S(t-3).k(t)            [3-step slack for its shuffle tree]
//   G1(t) = v(t-1)*kk1(t),  G2(t) = v(t-2)*kk2(t)   [loaded from g_kk]
//   out(t) = S(t).q(t) post-update (off-chain)
// ---------------------------------------------------------------------------
__device__ __forceinline__ float tree16(float s)
{
    s += __shfl_xor_sync(0xffffffffu, s, 1);
    s += __shfl_xor_sync(0xffffffffu, s, 2);
    s += __shfl_xor_sync(0xffffffffu, s, 4);
    s += __shfl_xor_sync(0xffffffffu, s, 8);
    return s;
}

__device__ __forceinline__ float dot4(const float (&a)[4], const float (&b)[4])
{
    float s0 = a[0] * b[0];
    float s1 = a[1] * b[1];
    s0 = fmaf(a[2], b[2], s0);
    s1 = fmaf(a[3], b[3], s1);
    return s0 + s1;
}

__device__ __forceinline__ float sigmoid_neg_l2(float z2)  // z2 = -log2(e)*z
{
    float e;
    asm("ex2.approx.f32 %0, %1;" : "=f"(e) : "f"(z2));
    float den = 1.0f + e;
    float r;
    asm("rcp.approx.f32 %0, %1;" : "=f"(r) : "f"(den));
    return r;
}

__device__ __forceinline__ void load_slot(const float* __restrict__ Pb,
                                          const float2* __restrict__ kkb,
                                          int t, int i, int lane16, float cb,
                                          float (&k)[4], float (&q)[4],
                                          float& v, float& c0,
                                          float& kk1, float& kk2)
{
    const float* p = Pb + (size_t)t * PSTRIDE;
    float4 kv = *(const float4*)(p + lane16 * 4);
    float4 qv = *(const float4*)(p + 128 + lane16 * 4);
    k[0] = kv.x; k[1] = kv.y; k[2] = kv.z; k[3] = kv.w;
    q[0] = qv.x; q[1] = qv.y; q[2] = qv.z; q[3] = qv.w;
    v  = p[64 + i];
    c0 = fmaf(-LOG2E, p[192 + i], cb);   // -log2(e)*(a + b_alpha)
    float2 kk = kkb[t];
    kk1 = kk.x; kk2 = kk.y;
}

__global__ __launch_bounds__(128, 1) void scan_kernel(
    const float* __restrict__ S0,
    const float* __restrict__ dA, const float* __restrict__ bA,
    float* __restrict__ out, float* __restrict__ Sout, int writeS)
{
    const int tid    = threadIdx.x;
    const int b      = blockIdx.x >> 3;                 // batch 0..15
    const int rb     = blockIdx.x & 7;                  // row block (8 rows)
    const int row    = tid >> 4;                        // local row 0..7
    const int lane16 = tid & 15;                        // col slice (4 cols)
    const int i      = rb * 8 + row;                    // global row 0..63

    const float*  Pb  = g_P + b * PROJ;
    const float2* kkb = g_kk + b * T_STEPS;
    const float cb  = -LOG2E * bA[i];
    const float c1  = -LOG2E * dA[i];

    float S[4];
    {
        float4 s = *(const float4*)(S0 + ((size_t)b * NDIM + i) * NDIM + lane16 * 4);
        S[0] = s.x; S[1] = s.y; S[2] = s.z; S[3] = s.w;
    }

    // ring-of-4 buffers
    float kb[4][4], qb[4][4], vb[4], c0b[4], kk1b[4], kk2b[4];
    float Ar[4];
#pragma unroll
    for (int s = 0; s < 4; s++)
        load_slot(Pb, kkb, s, i, lane16, cb,
                  kb[s], qb[s], vb[s], c0b[s], kk1b[s], kk2b[s]);

    Ar[0] = 0.0f;                        // A(4): written at step 1
    Ar[1] = tree16(dot4(S, kb[1]));      // A(1) = S0.k(1)
    Ar[2] = tree16(dot4(S, kb[2]));      // A(2) = S0.k(2)
    Ar[3] = 0.0f;                        // A(3): written at step 0

    // virtual history: alpha(-1)=alpha(-2)=1, v(-1)=v(-2)=0
    float alpha_prev = 1.0f;
    float vprev      = 0.0f;
    float dM         = tree16(dot4(S, kb[0]));   // M(0)-G1(0) = S0.k(0)
    float G1cur      = 0.0f;
    float c0cur      = c0b[0];

    float* orow = out + (size_t)b * NDIM + i;

#pragma unroll 1
    for (int t = 0; t < T_STEPS; t += 4) {
#pragma unroll
        for (int c = 0; c < 4; c++) {
            const int tt  = t + c;
            const int cn  = (c + 1) & 3;
            const int cp3 = (c + 3) & 3;
            const float vcur = vb[c];

            // ---- off-chain: vk, D = S - vk ----
            float vk[4], D[4];
#pragma unroll
            for (int j = 0; j < 4; j++) vk[j] = vcur * kb[c][j];
#pragma unroll
            for (int j = 0; j < 4; j++) D[j] = S[j] - vk[j];

            // ---- carried chain: alpha(t) ----
            float retrieved = fmaf(alpha_prev, dM, G1cur);
            float z2        = fmaf(c1, retrieved, c0cur);
            float alpha     = sigmoid_neg_l2(z2);

            // ---- M(t+1) branch (uses alpha_prev, NOT alpha) ----
            float G2n   = vprev * kk2b[cn];
            float Mnext = fmaf(alpha_prev, Ar[cn] - G2n, G2n);

            // ---- S(t) = alpha*D + vk ----
#pragma unroll
            for (int j = 0; j < 4; j++) S[j] = fmaf(alpha, D[j], vk[j]);

            // ---- A(t+3) = S(t).k(t+3)  (3-step slack) ----
            Ar[cp3] = tree16(dot4(S, kb[cp3]));

            // ---- out(t) = S(t).q(t), off-chain ----
            float o   = tree16(dot4(S, qb[c]));
            float res = o * o * sigmoid_neg_l2(-LOG2E * o);
            if (lane16 == 0)
                orow[(size_t)tt * (BATCH * NDIM)] = res;

            // ---- refill slot c with step tt+4 (kk dots precomputed!) ----
            {
                int t4 = tt + 4; if (t4 > T_STEPS - 1) t4 = T_STEPS - 1;
                load_slot(Pb, kkb, t4, i, lane16, cb,
                          kb[c], qb[c], vb[c], c0b[c], kk1b[c], kk2b[c]);
                int tp = tt + 16; if (tp > T_STEPS - 1) tp = T_STEPS - 1;
                const float* pf = Pb + (size_t)tp * PSTRIDE + (tid & 31) * 8;
                asm volatile("prefetch.global.L2 [%0];" :: "l"(pf));
            }

            // ---- carries for step t+1 ----
            float G1n = vcur * kk1b[cn];     // v(t)*k(t).k(t+1)
            dM        = Mnext - G1n;
            G1cur     = G1n;
            vprev     = vcur;
            alpha_prev = alpha;
            c0cur     = c0b[cn];
        }
    }

    if (writeS) {
        float* sp = Sout + ((size_t)b * NDIM + i) * NDIM + lane16 * 4;
        *(float4*)sp = make_float4(S[0], S[1], S[2], S[3]);
    }
}

// ---------------------------------------------------------------------------
extern "C" void kernel_launch(void* const* d_in, const int* in_sizes, int n_in,
                              void* d_out, int out_size)
{
    const float* x  = (const float*)d_in[0];
    const float* S0 = (const float*)d_in[1];
    const float* Wk = (const float*)d_in[2];
    const float* Wv = (const float*)d_in[3];
    const float* Wq = (const float*)d_in[4];
    const float* Wa = (const float*)d_in[5];
    const float* dA = (const float*)d_in[6];
    const float* bA = (const float*)d_in[7];

    float* out = (float*)d_out;
    const size_t out_elems = (size_t)T_STEPS * BATCH * NDIM;          // 2,097,152
    const size_t s_elems   = (size_t)BATCH * NDIM * NDIM;             //    65,536
    int writeS = ((size_t)out_size >= out_elems + s_elems) ? 1 : 0;
    float* Sout = out + out_elems;

    dim3 grid_g(T_STEPS * BATCH / 128, 4);   // (256, 4)
    proj_gemm<<<grid_g, 128>>>(x, Wk, Wv, Wq, Wa);

    kk_kernel<<<BATCH * T_STEPS * 32 / 256, 256>>>();   // 4096 blocks

    scan_kernel<<<128, 128>>>(S0, dA, bA, out, Sout, writeS);
}

// round 12
// speedup vs baseline: 1.5070x; 1.3261x over previous
#include <cuda_runtime.h>
#include <cstdint>
#include <cstddef>

// Problem constants
#define T_STEPS 2048
#define BATCH   16
#define DIM     1024
#define NDIM    64
#define PROJ    256            // 4 * NDIM (k, v, q, a)
#define PSTRIDE 4096           // floats per time step = BATCH * PROJ
#define LOG2E   1.44269504f

// Scratch: projections P[(t*BATCH + b)*256 + c], c = {k:0..63, v:64..127, q:128..191, a:192..255}
__device__ float  g_P[(size_t)T_STEPS * BATCH * PROJ];   // 33.5 MB
__device__ float2 g_kk[(size_t)BATCH * T_STEPS];         // (k(t-1).k(t), k(t-2).k(t))

// ---------------------------------------------------------------------------
// Kernel 1: projection GEMM on tensor cores (mma.sync m16n8k16 bf16,
// split-precision x = hi + lo, W = hi + lo; 3 passes accumulate in fp32).
// BM=128, BN=64 (one W per blockIdx.x), BK=32, 256 threads = 8 warps,
// warp tile 32x32.  grid = (4 proj, 256 m-chunks): proj fastest -> L2 x reuse.
// ---------------------------------------------------------------------------
#define ASTRIDE 17   // u32 per smem row (= 34 bf16, padded for banks)

#define MMA16816(d, a, b)                                                  \
    asm volatile("mma.sync.aligned.m16n8k16.row.col.f32.bf16.bf16.f32 "    \
        "{%0,%1,%2,%3}, {%4,%5,%6,%7}, {%8,%9}, {%0,%1,%2,%3};"            \
        : "+f"((d)[0]), "+f"((d)[1]), "+f"((d)[2]), "+f"((d)[3])           \
        : "r"((a)[0]), "r"((a)[1]), "r"((a)[2]), "r"((a)[3]),              \
          "r"((b)[0]), "r"((b)[1]))

__device__ __forceinline__ uint32_t cvt_bf16x2(float lo_elem, float hi_elem)
{
    uint32_t d;  // d.lo = lo_elem, d.hi = hi_elem
    asm("cvt.rn.bf16x2.f32 %0, %1, %2;" : "=r"(d) : "f"(hi_elem), "f"(lo_elem));
    return d;
}

__global__ __launch_bounds__(256) void proj_gemm_mma(
    const float* __restrict__ x,
    const float* __restrict__ Wk, const float* __restrict__ Wv,
    const float* __restrict__ Wq, const float* __restrict__ Wa)
{
    __shared__ __align__(16) uint32_t sAh[128 * ASTRIDE];
    __shared__ __align__(16) uint32_t sAl[128 * ASTRIDE];
    __shared__ __align__(16) uint32_t sWh[64 * ASTRIDE];
    __shared__ __align__(16) uint32_t sWl[64 * ASTRIDE];

    const int tid  = threadIdx.x;
    const int proj = blockIdx.x;
    const int m0   = blockIdx.y * 128;
    const float* W = (proj == 0) ? Wk : (proj == 1) ? Wv :
                     (proj == 2) ? Wq : Wa;

    const int lane = tid & 31;
    const int wid  = tid >> 5;
    const int wm   = (wid & 3) * 32;    // warp M offset (4 warps in M)
    const int wn   = (wid >> 2) * 32;   // warp N offset (2 warps in N)
    const int fr   = lane >> 2;         // fragment row 0..7
    const int fc   = lane & 3;          // fragment k-pair 0..3

    // loader geometry
    const int ar  = tid >> 1;           // x row 0..127
    const int aks = (tid & 1) * 16;     // x k-offset
    const int wr  = tid >> 2;           // W row 0..63
    const int wks = (tid & 3) * 8;      // W k-offset

    const float* xrow = x + (size_t)(m0 + ar) * DIM + aks;
    const float* wrow = W + (size_t)wr * DIM + wks;

    float acc[2][4][4];
#pragma unroll
    for (int mt = 0; mt < 2; mt++)
#pragma unroll
        for (int nt = 0; nt < 4; nt++)
#pragma unroll
            for (int j = 0; j < 4; j++) acc[mt][nt][j] = 0.0f;

    for (int k0 = 0; k0 < DIM; k0 += 32) {
        float4 xa0 = *(const float4*)(xrow + k0);
        float4 xa1 = *(const float4*)(xrow + k0 + 4);
        float4 xa2 = *(const float4*)(xrow + k0 + 8);
        float4 xa3 = *(const float4*)(xrow + k0 + 12);
        float4 wa0 = *(const float4*)(wrow + k0);
        float4 wa1 = *(const float4*)(wrow + k0 + 4);

        __syncthreads();   // previous tile fully consumed

        {   // split-convert + store x tile (16 elems -> 8 bf16x2 hi + 8 lo)
            float e[16];
            *(float4*)(e)      = xa0; *(float4*)(e + 4)  = xa1;
            *(float4*)(e + 8)  = xa2; *(float4*)(e + 12) = xa3;
            uint32_t base = ar * ASTRIDE + (aks >> 1);
#pragma unroll
            for (int p = 0; p < 8; p++) {
                float a0 = e[2 * p], a1 = e[2 * p + 1];
                uint32_t h = cvt_bf16x2(a0, a1);
                float r0 = a0 - __uint_as_float(h << 16);
                float r1 = a1 - __uint_as_float(h & 0xffff0000u);
                sAh[base + p] = h;
                sAl[base + p] = cvt_bf16x2(r0, r1);
            }
        }
        {   // split-convert + store W tile (8 elems -> 4 + 4)
            float e[8];
            *(float4*)(e)     = wa0; *(float4*)(e + 4) = wa1;
            uint32_t base = wr * ASTRIDE + (wks >> 1);
#pragma unroll
            for (int p = 0; p < 4; p++) {
                float a0 = e[2 * p], a1 = e[2 * p + 1];
                uint32_t h = cvt_bf16x2(a0, a1);
                float r0 = a0 - __uint_as_float(h << 16);
                float r1 = a1 - __uint_as_float(h & 0xffff0000u);
                sWh[base + p] = h;
                sWl[base + p] = cvt_bf16x2(r0, r1);
            }
        }
        __syncthreads();

#pragma unroll
        for (int kk = 0; kk < 32; kk += 16) {
            const int kw = (kk >> 1) + fc;    // u32 column within row
            uint32_t ah[2][4], al[2][4], bh[4][2], bl[4][2];
#pragma unroll
            for (int mt = 0; mt < 2; mt++) {
                int base = (wm + mt * 16 + fr) * ASTRIDE + kw;
                ah[mt][0] = sAh[base];
                ah[mt][1] = sAh[base + 8 * ASTRIDE];
                ah[mt][2] = sAh[base + 4];
                ah[mt][3] = sAh[base + 8 * ASTRIDE + 4];
                al[mt][0] = sAl[base];
                al[mt][1] = sAl[base + 8 * ASTRIDE];
                al[mt][2] = sAl[base + 4];
                al[mt][3] = sAl[base + 8 * ASTRIDE + 4];
            }
#pragma unroll
            for (int nt = 0; nt < 4; nt++) {
                int base = (wn + nt * 8 + fr) * ASTRIDE + kw;
                bh[nt][0] = sWh[base]; bh[nt][1] = sWh[base + 4];
                bl[nt][0] = sWl[base]; bl[nt][1] = sWl[base + 4];
            }
#pragma unroll
            for (int mt = 0; mt < 2; mt++)
#pragma unroll
                for (int nt = 0; nt < 4; nt++) {
                    MMA16816(acc[mt][nt], ah[mt], bh[nt]);   // hi*hi
                    MMA16816(acc[mt][nt], al[mt], bh[nt]);   // lo*hi
                    MMA16816(acc[mt][nt], ah[mt], bl[nt]);   // hi*lo
                }
        }
    }

    // epilogue: fragment -> g_P
#pragma unroll
    for (int mt = 0; mt < 2; mt++)
#pragma unroll
        for (int nt = 0; nt < 4; nt++) {
            int row = m0 + wm + mt * 16 + fr;
            int col = proj * 64 + wn + nt * 8 + fc * 2;
            *(float2*)(g_P + (size_t)row * PROJ + col) =
                make_float2(acc[mt][nt][0], acc[mt][nt][1]);
            *(float2*)(g_P + (size_t)(row + 8) * PROJ + col) =
                make_float2(acc[mt][nt][2], acc[mt][nt][3]);
        }
}

// ---------------------------------------------------------------------------
// Kernel 1b: row-independent k.k lookahead dots.
//   g_kk[b][t] = ( k(t-1).k(t),  k(t-2).k(t) )   (0 where t-1/t-2 < 0)
// ---------------------------------------------------------------------------
__global__ __launch_bounds__(256) void kk_kernel()
{
    const int w    = (blockIdx.x * 256 + threadIdx.x) >> 5;   // global warp
    const int lane = threadIdx.x & 31;
    const int b    = w >> 11;          // 2048 warps per batch
    const int t    = w & 2047;

    const float* kt = g_P + b * PROJ + (size_t)t * PSTRIDE;
    float2 k0 = *(const float2*)(kt + lane * 2);
    float2 k1 = make_float2(0.f, 0.f);
    float2 k2 = make_float2(0.f, 0.f);
    if (t >= 1) k1 = *(const float2*)(kt - PSTRIDE + lane * 2);
    if (t >= 2) k2 = *(const float2*)(kt - 2 * PSTRIDE + lane * 2);

    float d1 = fmaf(k0.y, k1.y, k0.x * k1.x);
    float d2 = fmaf(k0.y, k2.y, k0.x * k2.x);
#pragma unroll
    for (int m = 1; m < 32; m <<= 1) {
        d1 += __shfl_xor_sync(0xffffffffu, d1, m);
        d2 += __shfl_xor_sync(0xffffffffu, d2, m);
    }
    if (lane == 0)
        g_kk[b * T_STEPS + t] = make_float2(d1, d2);
}

// ---------------------------------------------------------------------------
// Kernel 2: scan (R10 version — 16 lanes/row, two-step lookahead,
// precomputed k.k dots; 2 shuffle trees per step).
// ---------------------------------------------------------------------------
__device__ __forceinline__ float tree16(float s)
{
    s += __shfl_xor_sync(0xffffffffu, s, 1);
    s += __shfl_xor_sync(0xffffffffu, s, 2);
    s += __shfl_xor_sync(0xffffffffu, s, 4);
    s += __shfl_xor_sync(0xffffffffu, s, 8);
    return s;
}

__device__ __forceinline__ float dot4(const float (&a)[4], const float (&b)[4])
{
    float s0 = a[0] * b[0];
    float s1 = a[1] * b[1];
    s0 = fmaf(a[2], b[2], s0);
    s1 = fmaf(a[3], b[3], s1);
    return s0 + s1;
}

__device__ __forceinline__ float sigmoid_neg_l2(float z2)  // z2 = -log2(e)*z
{
    float e;
    asm("ex2.approx.f32 %0, %1;" : "=f"(e) : "f"(z2));
    float den = 1.0f + e;
    float r;
    asm("rcp.approx.f32 %0, %1;" : "=f"(r) : "f"(den));
    return r;
}

__device__ __forceinline__ void load_slot(const float* __restrict__ Pb,
                                          const float2* __restrict__ kkb,
                                          int t, int i, int lane16, float cb,
                                          float (&k)[4], float (&q)[4],
                                          float& v, float& c0,
                                          float& kk1, float& kk2)
{
    const float* p = Pb + (size_t)t * PSTRIDE;
    float4 kv = *(const float4*)(p + lane16 * 4);
    float4 qv = *(const float4*)(p + 128 + lane16 * 4);
    k[0] = kv.x; k[1] = kv.y; k[2] = kv.z; k[3] = kv.w;
    q[0] = qv.x; q[1] = qv.y; q[2] = qv.z; q[3] = qv.w;
    v  = p[64 + i];
    c0 = fmaf(-LOG2E, p[192 + i], cb);   // -log2(e)*(a + b_alpha)
    float2 kk = kkb[t];
    kk1 = kk.x; kk2 = kk.y;
}

__global__ __launch_bounds__(128, 1) void scan_kernel(
    const float* __restrict__ S0,
    const float* __restrict__ dA, const float* __restrict__ bA,
    float* __restrict__ out, float* __restrict__ Sout, int writeS)
{
    const int tid    = threadIdx.x;
    const int b      = blockIdx.x >> 3;                 // batch 0..15
    const int rb     = blockIdx.x & 7;                  // row block (8 rows)
    const int row    = tid >> 4;                        // local row 0..7
    const int lane16 = tid & 15;                        // col slice (4 cols)
    const int i      = rb * 8 + row;                    // global row 0..63

    const float*  Pb  = g_P + b * PROJ;
    const float2* kkb = g_kk + b * T_STEPS;
    const float cb  = -LOG2E * bA[i];
    const float c1  = -LOG2E * dA[i];

    float S[4];
    {
        float4 s = *(const float4*)(S0 + ((size_t)b * NDIM + i) * NDIM + lane16 * 4);
        S[0] = s.x; S[1] = s.y; S[2] = s.z; S[3] = s.w;
    }

    // ring-of-4 buffers
    float kb[4][4], qb[4][4], vb[4], c0b[4], kk1b[4], kk2b[4];
    float Ar[4];
#pragma unroll
    for (int s = 0; s < 4; s++)
        load_slot(Pb, kkb, s, i, lane16, cb,
                  kb[s], qb[s], vb[s], c0b[s], kk1b[s], kk2b[s]);

    Ar[0] = 0.0f;                        // A(4): written at step 1
    Ar[1] = tree16(dot4(S, kb[1]));      // A(1) = S0.k(1)
    Ar[2] = tree16(dot4(S, kb[2]));      // A(2) = S0.k(2)
    Ar[3] = 0.0f;                        // A(3): written at step 0

    // virtual history: alpha(-1)=alpha(-2)=1, v(-1)=v(-2)=0
    float alpha_prev = 1.0f;
    float vprev      = 0.0f;
    float dM         = tree16(dot4(S, kb[0]));   // M(0)-G1(0) = S0.k(0)
    float G1cur      = 0.0f;
    float c0cur      = c0b[0];

    float* orow = out + (size_t)b * NDIM + i;

#pragma unroll 1
    for (int t = 0; t < T_STEPS; t += 4) {
#pragma unroll
        for (int c = 0; c < 4; c++) {
            const int tt  = t + c;
            const int cn  = (c + 1) & 3;
            const int cp3 = (c + 3) & 3;
            const float vcur = vb[c];

            // ---- off-chain: vk, D = S - vk ----
            float vk[4], D[4];
#pragma unroll
            for (int j = 0; j < 4; j++) vk[j] = vcur * kb[c][j];
#pragma unroll
            for (int j = 0; j < 4; j++) D[j] = S[j] - vk[j];

            // ---- carried chain: alpha(t) ----
            float retrieved = fmaf(alpha_prev, dM, G1cur);
            float z2        = fmaf(c1, retrieved, c0cur);
            float alpha     = sigmoid_neg_l2(z2);

            // ---- M(t+1) branch (uses alpha_prev, NOT alpha) ----
            float G2n   = vprev * kk2b[cn];
            float Mnext = fmaf(alpha_prev, Ar[cn] - G2n, G2n);

            // ---- S(t) = alpha*D + vk ----
#pragma unroll
            for (int j = 0; j < 4; j++) S[j] = fmaf(alpha, D[j], vk[j]);

            // ---- A(t+3) = S(t).k(t+3)  (3-step slack) ----
            Ar[cp3] = tree16(dot4(S, kb[cp3]));

            // ---- out(t) = S(t).q(t), off-chain ----
            float o   = tree16(dot4(S, qb[c]));
            float res = o * o * sigmoid_neg_l2(-LOG2E * o);
            if (lane16 == 0)
                orow[(size_t)tt * (BATCH * NDIM)] = res;

            // ---- refill slot c with step tt+4 (kk dots precomputed) ----
            {
                int t4 = tt + 4; if (t4 > T_STEPS - 1) t4 = T_STEPS - 1;
                load_slot(Pb, kkb, t4, i, lane16, cb,
                          kb[c], qb[c], vb[c], c0b[c], kk1b[c], kk2b[c]);
                int tp = tt + 16; if (tp > T_STEPS - 1) tp = T_STEPS - 1;
                const float* pf = Pb + (size_t)tp * PSTRIDE + (tid & 31) * 8;
                asm volatile("prefetch.global.L2 [%0];" :: "l"(pf));
            }

            // ---- carries for step t+1 ----
            float G1n = vcur * kk1b[cn];     // v(t)*k(t).k(t+1)
            dM        = Mnext - G1n;
            G1cur     = G1n;
            vprev     = vcur;
            alpha_prev = alpha;
            c0cur     = c0b[cn];
        }
    }

    if (writeS) {
        float* sp = Sout + ((size_t)b * NDIM + i) * NDIM + lane16 * 4;
        *(float4*)sp = make_float4(S[0], S[1], S[2], S[3]);
    }
}

// ---------------------------------------------------------------------------
extern "C" void kernel_launch(void* const* d_in, const int* in_sizes, int n_in,
                              void* d_out, int out_size)
{
    const float* x  = (const float*)d_in[0];
    const float* S0 = (const float*)d_in[1];
    const float* Wk = (const float*)d_in[2];
    const float* Wv = (const float*)d_in[3];
    const float* Wq = (const float*)d_in[4];
    const float* Wa = (const float*)d_in[5];
    const float* dA = (const float*)d_in[6];
    const float* bA = (const float*)d_in[7];

    float* out = (float*)d_out;
    const size_t out_elems = (size_t)T_STEPS * BATCH * NDIM;          // 2,097,152
    const size_t s_elems   = (size_t)BATCH * NDIM * NDIM;             //    65,536
    int writeS = ((size_t)out_size >= out_elems + s_elems) ? 1 : 0;
    float* Sout = out + out_elems;

    dim3 grid_g(4, 256);   // proj fastest -> 4 consumers of each x tile overlap in L2
    proj_gemm_mma<<<grid_g, 256>>>(x, Wk, Wv, Wq, Wa);

    kk_kernel<<<BATCH * T_STEPS * 32 / 256, 256>>>();   // 4096 blocks

    scan_kernel<<<128, 128>>>(S0, dA, bA, out, Sout, writeS);
}

// round 16
// speedup vs baseline: 1.5470x; 1.0265x over previous
#include <cuda_runtime.h>
#include <cstdint>
#include <cstddef>

// Problem constants
#define T_STEPS 2048
#define BATCH   16
#define DIM     1024
#define NDIM    64
#define PROJ    256            // 4 * NDIM (k, v, q, a)
#define PSTRIDE 4096           // floats per time step = BATCH * PROJ
#define LOG2E   1.44269504f

// Scratch: projections P[(t*BATCH + b)*256 + c], c = {k:0..63, v:64..127, q:128..191, a:192..255}
__device__ float  g_P[(size_t)T_STEPS * BATCH * PROJ];   // 33.5 MB
__device__ float2 g_kk[(size_t)BATCH * T_STEPS];         // (k(t-1).k(t), k(t-2).k(t))

// ---------------------------------------------------------------------------
// Kernel 1: projection GEMM on tensor cores (unchanged from R12).
// ---------------------------------------------------------------------------
#define ASTRIDE 17   // u32 per smem row (= 34 bf16, padded for banks)

#define MMA16816(d, a, b)                                                  \
    asm volatile("mma.sync.aligned.m16n8k16.row.col.f32.bf16.bf16.f32 "    \
        "{%0,%1,%2,%3}, {%4,%5,%6,%7}, {%8,%9}, {%0,%1,%2,%3};"            \
        : "+f"((d)[0]), "+f"((d)[1]), "+f"((d)[2]), "+f"((d)[3])           \
        : "r"((a)[0]), "r"((a)[1]), "r"((a)[2]), "r"((a)[3]),              \
          "r"((b)[0]), "r"((b)[1]))

__device__ __forceinline__ uint32_t cvt_bf16x2(float lo_elem, float hi_elem)
{
    uint32_t d;  // d.lo = lo_elem, d.hi = hi_elem
    asm("cvt.rn.bf16x2.f32 %0, %1, %2;" : "=r"(d) : "f"(hi_elem), "f"(lo_elem));
    return d;
}

__global__ __launch_bounds__(256) void proj_gemm_mma(
    const float* __restrict__ x,
    const float* __restrict__ Wk, const float* __restrict__ Wv,
    const float* __restrict__ Wq, const float* __restrict__ Wa)
{
    __shared__ __align__(16) uint32_t sAh[128 * ASTRIDE];
    __shared__ __align__(16) uint32_t sAl[128 * ASTRIDE];
    __shared__ __align__(16) uint32_t sWh[64 * ASTRIDE];
    __shared__ __align__(16) uint32_t sWl[64 * ASTRIDE];

    const int tid  = threadIdx.x;
    const int proj = blockIdx.x;
    const int m0   = blockIdx.y * 128;
    const float* W = (proj == 0) ? Wk : (proj == 1) ? Wv :
                     (proj == 2) ? Wq : Wa;

    const int lane = tid & 31;
    const int wid  = tid >> 5;
    const int wm   = (wid & 3) * 32;    // warp M offset (4 warps in M)
    const int wn   = (wid >> 2) * 32;   // warp N offset (2 warps in N)
    const int fr   = lane >> 2;         // fragment row 0..7
    const int fc   = lane & 3;          // fragment k-pair 0..3

    const int ar  = tid >> 1;           // x row 0..127
    const int aks = (tid & 1) * 16;     // x k-offset
    const int wr  = tid >> 2;           // W row 0..63
    const int wks = (tid & 3) * 8;      // W k-offset

    const float* xrow = x + (size_t)(m0 + ar) * DIM + aks;
    const float* wrow = W + (size_t)wr * DIM + wks;

    float acc[2][4][4];
#pragma unroll
    for (int mt = 0; mt < 2; mt++)
#pragma unroll
        for (int nt = 0; nt < 4; nt++)
#pragma unroll
            for (int j = 0; j < 4; j++) acc[mt][nt][j] = 0.0f;

    for (int k0 = 0; k0 < DIM; k0 += 32) {
        float4 xa0 = *(const float4*)(xrow + k0);
        float4 xa1 = *(const float4*)(xrow + k0 + 4);
        float4 xa2 = *(const float4*)(xrow + k0 + 8);
        float4 xa3 = *(const float4*)(xrow + k0 + 12);
        float4 wa0 = *(const float4*)(wrow + k0);
        float4 wa1 = *(const float4*)(wrow + k0 + 4);

        __syncthreads();   // previous tile fully consumed

        {
            float e[16];
            *(float4*)(e)      = xa0; *(float4*)(e + 4)  = xa1;
            *(float4*)(e + 8)  = xa2; *(float4*)(e + 12) = xa3;
            uint32_t base = ar * ASTRIDE + (aks >> 1);
#pragma unroll
            for (int p = 0; p < 8; p++) {
                float a0 = e[2 * p], a1 = e[2 * p + 1];
                uint32_t h = cvt_bf16x2(a0, a1);
                float r0 = a0 - __uint_as_float(h << 16);
                float r1 = a1 - __uint_as_float(h & 0xffff0000u);
                sAh[base + p] = h;
                sAl[base + p] = cvt_bf16x2(r0, r1);
            }
        }
        {
            float e[8];
            *(float4*)(e)     = wa0; *(float4*)(e + 4) = wa1;
            uint32_t base = wr * ASTRIDE + (wks >> 1);
#pragma unroll
            for (int p = 0; p < 4; p++) {
                float a0 = e[2 * p], a1 = e[2 * p + 1];
                uint32_t h = cvt_bf16x2(a0, a1);
                float r0 = a0 - __uint_as_float(h << 16);
                float r1 = a1 - __uint_as_float(h & 0xffff0000u);
                sWh[base + p] = h;
                sWl[base + p] = cvt_bf16x2(r0, r1);
            }
        }
        __syncthreads();

#pragma unroll
        for (int kk = 0; kk < 32; kk += 16) {
            const int kw = (kk >> 1) + fc;
            uint32_t ah[2][4], al[2][4], bh[4][2], bl[4][2];
#pragma unroll
            for (int mt = 0; mt < 2; mt++) {
                int base = (wm + mt * 16 + fr) * ASTRIDE + kw;
                ah[mt][0] = sAh[base];
                ah[mt][1] = sAh[base + 8 * ASTRIDE];
                ah[mt][2] = sAh[base + 4];
                ah[mt][3] = sAh[base + 8 * ASTRIDE + 4];
                al[mt][0] = sAl[base];
                al[mt][1] = sAl[base + 8 * ASTRIDE];
                al[mt][2] = sAl[base + 4];
                al[mt][3] = sAl[base + 8 * ASTRIDE + 4];
            }
#pragma unroll
            for (int nt = 0; nt < 4; nt++) {
                int base = (wn + nt * 8 + fr) * ASTRIDE + kw;
                bh[nt][0] = sWh[base]; bh[nt][1] = sWh[base + 4];
                bl[nt][0] = sWl[base]; bl[nt][1] = sWl[base + 4];
            }
#pragma unroll
            for (int mt = 0; mt < 2; mt++)
#pragma unroll
                for (int nt = 0; nt < 4; nt++) {
                    MMA16816(acc[mt][nt], ah[mt], bh[nt]);   // hi*hi
                    MMA16816(acc[mt][nt], al[mt], bh[nt]);   // lo*hi
                    MMA16816(acc[mt][nt], ah[mt], bl[nt]);   // hi*lo
                }
        }
    }

#pragma unroll
    for (int mt = 0; mt < 2; mt++)
#pragma unroll
        for (int nt = 0; nt < 4; nt++) {
            int row = m0 + wm + mt * 16 + fr;
            int col = proj * 64 + wn + nt * 8 + fc * 2;
            *(float2*)(g_P + (size_t)row * PROJ + col) =
                make_float2(acc[mt][nt][0], acc[mt][nt][1]);
            *(float2*)(g_P + (size_t)(row + 8) * PROJ + col) =
                make_float2(acc[mt][nt][2], acc[mt][nt][3]);
        }
}

// ---------------------------------------------------------------------------
// Kernel 1b: row-independent k.k lookahead dots (unchanged from R10).
// ---------------------------------------------------------------------------
__global__ __launch_bounds__(256) void kk_kernel()
{
    const int w    = (blockIdx.x * 256 + threadIdx.x) >> 5;   // global warp
    const int lane = threadIdx.x & 31;
    const int b    = w >> 11;
    const int t    = w & 2047;

    const float* kt = g_P + b * PROJ + (size_t)t * PSTRIDE;
    float2 k0 = *(const float2*)(kt + lane * 2);
    float2 k1 = make_float2(0.f, 0.f);
    float2 k2 = make_float2(0.f, 0.f);
    if (t >= 1) k1 = *(const float2*)(kt - PSTRIDE + lane * 2);
    if (t >= 2) k2 = *(const float2*)(kt - 2 * PSTRIDE + lane * 2);

    float d1 = fmaf(k0.y, k1.y, k0.x * k1.x);
    float d2 = fmaf(k0.y, k2.y, k0.x * k2.x);
#pragma unroll
    for (int m = 1; m < 32; m <<= 1) {
        d1 += __shfl_xor_sync(0xffffffffu, d1, m);
        d2 += __shfl_xor_sync(0xffffffffu, d2, m);
    }
    if (lane == 0)
        g_kk[b * T_STEPS + t] = make_float2(d1, d2);
}

// ---------------------------------------------------------------------------
// Kernel 2: scan with CROSS-STEP PIPELINED shuffle trees.
// A(u)=S(u-3).k(u): dot+rnd1 at step u-3, rnds 2,3 at u-2, rnd4 at u-1 (use).
// o(t)=S(t).q(t):   dot+rnd1 at step t,   rnds 2,3 at t+1, rnd4+store at t+2.
// Per step: 8 independent-ish SHFLs, max 2 dependent back-to-back.
// Carried chain unchanged: fma -> fma -> ex2 -> add -> rcp.
// ---------------------------------------------------------------------------
#define SHX(v, m) __shfl_xor_sync(0xffffffffu, (v), (m))

__device__ __forceinline__ float dot4(const float (&a)[4], const float (&b)[4])
{
    float s0 = a[0] * b[0];
    float s1 = a[1] * b[1];
    s0 = fmaf(a[2], b[2], s0);
    s1 = fmaf(a[3], b[3], s1);
    return s0 + s1;
}

__device__ __forceinline__ float sigmoid_neg_l2(float z2)  // z2 = -log2(e)*z
{
    float e;
    asm("ex2.approx.f32 %0, %1;" : "=f"(e) : "f"(z2));
    float den = 1.0f + e;
    float r;
    asm("rcp.approx.f32 %0, %1;" : "=f"(r) : "f"(den));
    return r;
}

__device__ __forceinline__ void load_slot(const float* __restrict__ Pb,
                                          const float2* __restrict__ kkb,
                                          int t, int i, int lane16, float cb,
                                          float (&k)[4], float (&q)[4],
                                          float& v, float& c0,
                                          float& kk1, float& kk2)
{
    const float* p = Pb + (size_t)t * PSTRIDE;
    float4 kv = *(const float4*)(p + lane16 * 4);
    float4 qv = *(const float4*)(p + 128 + lane16 * 4);
    k[0] = kv.x; k[1] = kv.y; k[2] = kv.z; k[3] = kv.w;
    q[0] = qv.x; q[1] = qv.y; q[2] = qv.z; q[3] = qv.w;
    v  = p[64 + i];
    c0 = fmaf(-LOG2E, p[192 + i], cb);
    float2 kk = kkb[t];
    kk1 = kk.x; kk2 = kk.y;
}

__global__ __launch_bounds__(128, 1) void scan_kernel(
    const float* __restrict__ S0,
    const float* __restrict__ dA, const float* __restrict__ bA,
    float* __restrict__ out, float* __restrict__ Sout, int writeS)
{
    const int tid    = threadIdx.x;
    const int b      = blockIdx.x >> 3;                 // batch 0..15
    const int rb     = blockIdx.x & 7;                  // row block (8 rows)
    const int row    = tid >> 4;                        // local row 0..7
    const int lane16 = tid & 15;                        // col slice (4 cols)
    const int i      = rb * 8 + row;                    // global row 0..63

    const float*  Pb  = g_P + b * PROJ;
    const float2* kkb = g_kk + b * T_STEPS;
    const float cb  = -LOG2E * bA[i];
    const float c1  = -LOG2E * dA[i];

    float S[4];
    {
        float4 s = *(const float4*)(S0 + ((size_t)b * NDIM + i) * NDIM + lane16 * 4);
        S[0] = s.x; S[1] = s.y; S[2] = s.z; S[3] = s.w;
    }

    // ring-of-4 input buffers
    float kb[4][4], qb[4][4], vb[4], c0b[4], kk1b[4], kk2b[4];
#pragma unroll
    for (int s = 0; s < 4; s++)
        load_slot(Pb, kkb, s, i, lane16, cb,
                  kb[s], qb[s], vb[s], c0b[s], kk1b[s], kk2b[s]);

    // pipelined-tree state
    float a_s1[4], a_s3[4], Ar[4];          // A-tree: after rnd1 / rnd3 / final
    float o_s1[4], o_s3[4];                 // o-tree: after rnd1 / rnd3
#pragma unroll
    for (int s = 0; s < 4; s++) { a_s1[s] = a_s3[s] = Ar[s] = 0.0f;
                                  o_s1[s] = o_s3[s] = 0.0f; }

    // Prologue.
    // dM carries full tree of S0.k(0).
    {
        float d = dot4(S, kb[0]);
        d += SHX(d, 1); d += SHX(d, 2); d += SHX(d, 4); d += SHX(d, 8);
        // dM set below
        Ar[0] = d;   // unused slot, harmless
        // A(1): through round 3 (round 4 happens at step 0)
        float d1 = dot4(S, kb[1]);
        d1 += SHX(d1, 1); d1 += SHX(d1, 2); d1 += SHX(d1, 4);
        a_s3[1] = d1;
        // A(2): through round 1 (rounds 2,3 at step 0; round 4 at step 1)
        float d2 = dot4(S, kb[2]);
        a_s1[2] = d2 + SHX(d2, 1);
    }

    // virtual history: alpha(-1)=alpha(-2)=1, v(-1)=v(-2)=0
    float alpha_prev = 1.0f;
    float vprev      = 0.0f;
    float dM         = Ar[0];    // S0.k(0)
    float G1cur      = 0.0f;
    float c0cur      = c0b[0];

    float* orow = out + (size_t)b * NDIM + i;

#pragma unroll 1
    for (int t = 0; t < T_STEPS; t += 4) {
#pragma unroll
        for (int c = 0; c < 4; c++) {
            const int tt  = t + c;
            const int cn  = (c + 1) & 3;
            const int cp2 = (c + 2) & 3;
            const int cp3 = (c + 3) & 3;
            const float vcur = vb[c];

            // ---- finalize A(tt+1): round 4 (needed for Mnext below) ----
            Ar[cn] = a_s3[cn] + SHX(a_s3[cn], 8);

            // ---- rounds 2,3 of A(tt+2) ----
            {
                float s2 = a_s1[cp2] + SHX(a_s1[cp2], 2);
                a_s3[cp2] = s2 + SHX(s2, 4);
            }
            // ---- rounds 2,3 of o(tt-1) [slot cp3] ----
            {
                float s2 = o_s1[cp3] + SHX(o_s1[cp3], 2);
                o_s3[cp3] = s2 + SHX(s2, 4);
            }
            // ---- finalize o(tt-2) [slot cp2]: round 4 + output ----
            {
                float o   = o_s3[cp2] + SHX(o_s3[cp2], 8);
                float res = o * o * sigmoid_neg_l2(-LOG2E * o);
                if (tt >= 2 && lane16 == 0)
                    orow[(size_t)(tt - 2) * (BATCH * NDIM)] = res;
            }

            // ---- off-chain: vk, D = S - vk ----
            float vk[4], D[4];
#pragma unroll
            for (int j = 0; j < 4; j++) vk[j] = vcur * kb[c][j];
#pragma unroll
            for (int j = 0; j < 4; j++) D[j] = S[j] - vk[j];

            // ---- carried chain: alpha(tt) ----
            float retrieved = fmaf(alpha_prev, dM, G1cur);
            float z2        = fmaf(c1, retrieved, c0cur);
            float alpha     = sigmoid_neg_l2(z2);

            // ---- M(tt+1) branch (uses alpha_prev + finalized Ar[cn]) ----
            float G2n   = vprev * kk2b[cn];
            float Mnext = fmaf(alpha_prev, Ar[cn] - G2n, G2n);

            // ---- S(tt) = alpha*D + vk ----
#pragma unroll
            for (int j = 0; j < 4; j++) S[j] = fmaf(alpha, D[j], vk[j]);

            // ---- create A(tt+3): dot + round 1 ----
            {
                float d = dot4(S, kb[cp3]);
                a_s1[cp3] = d + SHX(d, 1);
            }
            // ---- create o(tt): dot + round 1 ----
            {
                float d = dot4(S, qb[c]);
                o_s1[c] = d + SHX(d, 1);
            }

            // ---- refill slot c with step tt+4 ----
            {
                int t4 = tt + 4; if (t4 > T_STEPS - 1) t4 = T_STEPS - 1;
                load_slot(Pb, kkb, t4, i, lane16, cb,
                          kb[c], qb[c], vb[c], c0b[c], kk1b[c], kk2b[c]);
            }

            // ---- carries for step tt+1 ----
            float G1n = vcur * kk1b[cn];
            dM        = Mnext - G1n;
            G1cur     = G1n;
            vprev     = vcur;
            alpha_prev = alpha;
            c0cur     = c0b[cn];
        }
    }

    // ---- drain: o(2046) [slot 2, o_s3 ready], o(2047) [slot 3, o_s1 ready] ----
    {
        float o   = o_s3[2] + SHX(o_s3[2], 8);
        float res = o * o * sigmoid_neg_l2(-LOG2E * o);
        if (lane16 == 0)
            orow[(size_t)(T_STEPS - 2) * (BATCH * NDIM)] = res;
    }
    {
        float s2 = o_s1[3] + SHX(o_s1[3], 2);
        float s3 = s2 + SHX(s2, 4);
        float o  = s3 + SHX(s3, 8);
        float res = o * o * sigmoid_neg_l2(-LOG2E * o);
        if (lane16 == 0)
            orow[(size_t)(T_STEPS - 1) * (BATCH * NDIM)] = res;
    }

    if (writeS) {
        float* sp = Sout + ((size_t)b * NDIM + i) * NDIM + lane16 * 4;
        *(float4*)sp = make_float4(S[0], S[1], S[2], S[3]);
    }
}

// ---------------------------------------------------------------------------
extern "C" void kernel_launch(void* const* d_in, const int* in_sizes, int n_in,
                              void* d_out, int out_size)
{
    const float* x  = (const float*)d_in[0];
    const float* S0 = (const float*)d_in[1];
    const float* Wk = (const float*)d_in[2];
    const float* Wv = (const float*)d_in[3];
    const float* Wq = (const float*)d_in[4];
    const float* Wa = (const float*)d_in[5];
    const float* dA = (const float*)d_in[6];
    const float* bA = (const float*)d_in[7];

    float* out = (float*)d_out;
    const size_t out_elems = (size_t)T_STEPS * BATCH * NDIM;          // 2,097,152
    const size_t s_elems   = (size_t)BATCH * NDIM * NDIM;             //    65,536
    int writeS = ((size_t)out_size >= out_elems + s_elems) ? 1 : 0;
    float* Sout = out + out_elems;

    dim3 grid_g(4, 256);   // proj fastest -> 4 consumers of each x tile overlap in L2
    proj_gemm_mma<<<grid_g, 256>>>(x, Wk, Wv, Wq, Wa);

    kk_kernel<<<BATCH * T_STEPS * 32 / 256, 256>>>();   // 4096 blocks

    scan_kernel<<<128, 128>>>(S0, dA, bA, out, Sout, writeS);
}